// round 1
// baseline (speedup 1.0000x reference)
#include <cuda_runtime.h>

// Problem constants (fixed shapes for this problem instance)
#define NCH      256
#define NB       2
#define NBOX     512
#define K_ROIS   1024   // NB * NBOX
#define OUTB     7
#define NSAMP    14     // OUT * SR
#define OUT_PER_ROI 12544  // 256*49
// channels-last scratch: sum over levels of B*H*W*C floats = 27,200,000 (108.8 MB)
__device__ float g_cl[27200000];

// ---------------------------------------------------------------------------
// Pass A: transpose [B,C,P] -> [B,P,C] per level (P = H*W), tiled via shared.
// ---------------------------------------------------------------------------
__global__ void transpose_k(const float* __restrict__ in, int P, int outOff)
{
    __shared__ float tile[32][33];
    const int p0 = blockIdx.x * 32;
    const int c0 = blockIdx.y * 32;
    const int b  = blockIdx.z;

    const float* src = in + (size_t)b * NCH * P;
    #pragma unroll
    for (int i = 0; i < 4; ++i) {
        int c = c0 + threadIdx.y + i * 8;
        int p = p0 + threadIdx.x;
        if (p < P)
            tile[threadIdx.y + i * 8][threadIdx.x] = src[(size_t)c * P + p];
    }
    __syncthreads();
    float* dst = g_cl + outOff + (size_t)b * P * NCH;
    #pragma unroll
    for (int i = 0; i < 4; ++i) {
        int p = p0 + threadIdx.y + i * 8;
        int c = c0 + threadIdx.x;
        if (p < P)
            dst[(size_t)p * NCH + c] = tile[threadIdx.x][threadIdx.y + i * 8];
    }
}

// ---------------------------------------------------------------------------
// Pass B: one block per ROI. 64 threads, thread t owns channels 4t..4t+3.
// Shared layout (floats):
//   [0,12544)            output staging tile, layout [c][49]
//   [12544,12544+784)    float4 weights per sample (196)
//   then int offsets per sample (196), then y/x precompute arrays (84)
// total 13608 floats = 54432 bytes (dynamic smem, opt-in > 48KB)
// ---------------------------------------------------------------------------
#define SMEM_FLOATS 13608
#define SMEM_BYTES  (SMEM_FLOATS * 4)

__global__ __launch_bounds__(64) void roi_kernel(const float* __restrict__ boxes,
                                                 float* __restrict__ out)
{
    extern __shared__ float smem[];
    float*  stage = smem;                          // 12544
    float4* wsm   = (float4*)(smem + 12544);       // 196 float4 (16B aligned: 12544*4=50176)
    int*    offsm = (int*)(smem + 12544 + 784);    // 196
    int*    ylsm  = offsm + 196;                   // 14
    int*    xlsm  = ylsm + 14;                     // 14
    float*  lysm  = (float*)(xlsm + 14);           // 14
    float*  lxsm  = lysm + 14;                     // 14
    float*  vysm  = lxsm + 14;                     // 14
    float*  vxsm  = vysm + 14;                     // 14

    const int k   = blockIdx.x;
    const int tid = threadIdx.x;
    const int b   = k >> 9;   // k / NBOX

    // --- box metadata (computed redundantly by every thread; trivial) ---
    const float x1 = boxes[k * 4 + 0];
    const float y1 = boxes[k * 4 + 1];
    const float x2 = boxes[k * 4 + 2];
    const float y2 = boxes[k * 4 + 3];

    const float area = (x2 - x1) * (y2 - y1);
    const float sbox = sqrtf(fmaxf(area, 0.0f));
    const float lf   = floorf(4.0f + log2f(sbox / 224.0f) + 1e-6f);
    const int   lvl  = (int)fminf(fmaxf(lf, 2.0f), 5.0f) - 2;

    const int   HS[4]  = {200, 100, 50, 25};
    const float SCL[4] = {0.25f, 0.125f, 0.0625f, 0.03125f};
    const int   OFF[4] = {0, 20480000, 25600000, 26880000};

    const int   H  = HS[lvl];
    const int   W  = H;
    const float sc = SCL[lvl];

    const float bx1 = x1 * sc, by1 = y1 * sc;
    const float bx2 = x2 * sc, by2 = y2 * sc;
    const float rw  = fmaxf(bx2 - bx1, 1.0f);
    const float rh  = fmaxf(by2 - by1, 1.0f);
    const float bw  = rw * (1.0f / 7.0f);
    const float bh  = rh * (1.0f / 7.0f);

    // --- phase 1: separable y / x sample precompute ---
    if (tid < 14) {
        const int iy = tid;
        const float y = by1 + (float)(iy >> 1) * bh + ((float)(iy & 1) + 0.5f) * bh * 0.5f;
        const float v = (y >= -1.0f && y <= (float)H) ? 1.0f : 0.0f;
        const float yc = fminf(fmaxf(y, 0.0f), (float)(H - 1));
        int yl = (int)floorf(yc);
        if (yl > H - 2) yl = H - 2;
        ylsm[iy] = yl;
        lysm[iy] = yc - (float)yl;
        vysm[iy] = v;
    } else if (tid >= 32 && tid < 46) {
        const int ix = tid - 32;
        const float x = bx1 + (float)(ix >> 1) * bw + ((float)(ix & 1) + 0.5f) * bw * 0.5f;
        const float v = (x >= -1.0f && x <= (float)W) ? 1.0f : 0.0f;
        const float xc = fminf(fmaxf(x, 0.0f), (float)(W - 1));
        int xl = (int)floorf(xc);
        if (xl > W - 2) xl = W - 2;
        xlsm[ix] = xl;
        lxsm[ix] = xc - (float)xl;
        vxsm[ix] = v;
    }
    __syncthreads();

    // --- phase 2: per-sample combined offset + 4 bilinear weights ---
    for (int ss = tid; ss < NSAMP * NSAMP; ss += 64) {
        const int iy = ss / NSAMP;
        const int ix = ss - iy * NSAMP;
        const float ly = lysm[iy], lx = lxsm[ix];
        const float v  = vysm[iy] * vxsm[ix];
        const float hy = 1.0f - ly, hx = 1.0f - lx;
        wsm[ss]   = make_float4(hy * hx * v, hy * lx * v, ly * hx * v, ly * lx * v);
        offsm[ss] = (ylsm[iy] * W + xlsm[ix]) * NCH;
    }
    __syncthreads();

    // --- phase 3: accumulate 49 bins, 4 channels per thread, coalesced taps ---
    const float* fb = g_cl + OFF[lvl] + (size_t)b * H * W * NCH + tid * 4;
    const int rs = W * NCH;   // +1 feature row in floats

    for (int ph = 0; ph < 7; ++ph) {
        for (int pw = 0; pw < 7; ++pw) {
            float4 acc = make_float4(0.f, 0.f, 0.f, 0.f);
            #pragma unroll
            for (int sub = 0; sub < 4; ++sub) {
                const int sI = (ph * 2 + (sub >> 1)) * NSAMP + (pw * 2 + (sub & 1));
                const float4 w = wsm[sI];
                const int    o = offsm[sI];
                const float4* p0 = (const float4*)(fb + o);
                const float4* p1 = (const float4*)(fb + o + rs);
                const float4 v00 = p0[0];
                const float4 v01 = p0[64];   // +256 floats = next x
                const float4 v10 = p1[0];
                const float4 v11 = p1[64];
                acc.x += w.x * v00.x + w.y * v01.x + w.z * v10.x + w.w * v11.x;
                acc.y += w.x * v00.y + w.y * v01.y + w.z * v10.y + w.w * v11.y;
                acc.z += w.x * v00.z + w.y * v01.z + w.z * v10.z + w.w * v11.z;
                acc.w += w.x * v00.w + w.y * v01.w + w.z * v10.w + w.w * v11.w;
            }
            const int base = (tid * 4) * 49 + ph * 7 + pw;
            stage[base      ] = acc.x * 0.25f;
            stage[base +  49] = acc.y * 0.25f;
            stage[base +  98] = acc.z * 0.25f;
            stage[base + 147] = acc.w * 0.25f;
        }
    }
    __syncthreads();

    // --- phase 4: fully coalesced float4 writeback of the ROI tile ---
    float4* op = (float4*)(out + (size_t)k * OUT_PER_ROI);
    const float4* sp = (const float4*)stage;
    for (int v = tid; v < OUT_PER_ROI / 4; v += 64)
        op[v] = sp[v];
}

// ---------------------------------------------------------------------------
extern "C" void kernel_launch(void* const* d_in, const int* in_sizes, int n_in,
                              void* d_out, int out_size)
{
    (void)in_sizes; (void)n_in; (void)out_size;
    const float* boxes = (const float*)d_in[4];
    float* out = (float*)d_out;

    cudaFuncSetAttribute(roi_kernel,
                         cudaFuncAttributeMaxDynamicSharedMemorySize, SMEM_BYTES);

    const int P[4]    = {40000, 10000, 2500, 625};
    const int OFFh[4] = {0, 20480000, 25600000, 26880000};
    for (int l = 0; l < 4; ++l) {
        dim3 grid((P[l] + 31) / 32, NCH / 32, NB);
        transpose_k<<<grid, dim3(32, 8)>>>((const float*)d_in[l], P[l], OFFh[l]);
    }

    roi_kernel<<<K_ROIS, 64, SMEM_BYTES>>>(boxes, out);
}

// round 2
// speedup vs baseline: 1.7245x; 1.7245x over previous
#include <cuda_runtime.h>

// Problem constants (fixed shapes for this problem instance)
#define NCH      256
#define NB       2
#define NBOX     512
#define K_ROIS   1024   // NB * NBOX
#define OUTB     7
#define NSAMP    14     // OUT * SR
#define OUT_PER_ROI 12544  // 256*49
// channels-last scratch: sum over levels of B*H*W*C floats = 27,200,000 (108.8 MB)
__device__ float g_cl[27200000];

// ---------------------------------------------------------------------------
// Pass A: transpose [B,C,P] -> [B,P,C] per level (P = H*W), tiled via shared.
// ---------------------------------------------------------------------------
__global__ void transpose_k(const float* __restrict__ in, int P, int outOff)
{
    __shared__ float tile[32][33];
    const int p0 = blockIdx.x * 32;
    const int c0 = blockIdx.y * 32;
    const int b  = blockIdx.z;

    const float* src = in + (size_t)b * NCH * P;
    #pragma unroll
    for (int i = 0; i < 4; ++i) {
        int c = c0 + threadIdx.y + i * 8;
        int p = p0 + threadIdx.x;
        if (p < P)
            tile[threadIdx.y + i * 8][threadIdx.x] = src[(size_t)c * P + p];
    }
    __syncthreads();
    float* dst = g_cl + outOff + (size_t)b * P * NCH;
    #pragma unroll
    for (int i = 0; i < 4; ++i) {
        int p = p0 + threadIdx.y + i * 8;
        int c = c0 + threadIdx.x;
        if (p < P)
            dst[(size_t)p * NCH + c] = tile[threadIdx.x][threadIdx.y + i * 8];
    }
}

// ---------------------------------------------------------------------------
// Pass B: one block per ROI. 256 threads:
//   tid & 63  -> channel group (4 consecutive channels, float4)
//   tid >> 6  -> bin group (handles bins bg, bg+4, bg+8, ... of the 49 bins)
// Shared layout (floats):
//   [0,12544)            output staging tile, layout [c][49]
//   [12544,12544+784)    float4 weights per sample (196)
//   then int offsets per sample (196), then y/x precompute arrays (84)
// total 13608 floats = 54432 bytes (dynamic smem, opt-in > 48KB)
// ---------------------------------------------------------------------------
#define SMEM_FLOATS 13608
#define SMEM_BYTES  (SMEM_FLOATS * 4)

__global__ __launch_bounds__(256) void roi_kernel(const float* __restrict__ boxes,
                                                  float* __restrict__ out)
{
    extern __shared__ float smem[];
    float*  stage = smem;                          // 12544
    float4* wsm   = (float4*)(smem + 12544);       // 196 float4 (16B aligned: 12544*4=50176)
    int*    offsm = (int*)(smem + 12544 + 784);    // 196
    int*    ylsm  = offsm + 196;                   // 14
    int*    xlsm  = ylsm + 14;                     // 14
    float*  lysm  = (float*)(xlsm + 14);           // 14
    float*  lxsm  = lysm + 14;                     // 14
    float*  vysm  = lxsm + 14;                     // 14
    float*  vxsm  = vysm + 14;                     // 14

    const int k   = blockIdx.x;
    const int tid = threadIdx.x;
    const int b   = k >> 9;   // k / NBOX

    // --- box metadata (computed redundantly by every thread; trivial) ---
    const float x1 = boxes[k * 4 + 0];
    const float y1 = boxes[k * 4 + 1];
    const float x2 = boxes[k * 4 + 2];
    const float y2 = boxes[k * 4 + 3];

    const float area = (x2 - x1) * (y2 - y1);
    const float sbox = sqrtf(fmaxf(area, 0.0f));
    const float lf   = floorf(4.0f + log2f(sbox / 224.0f) + 1e-6f);
    const int   lvl  = (int)fminf(fmaxf(lf, 2.0f), 5.0f) - 2;

    const int   HS[4]  = {200, 100, 50, 25};
    const float SCL[4] = {0.25f, 0.125f, 0.0625f, 0.03125f};
    const int   OFF[4] = {0, 20480000, 25600000, 26880000};

    const int   H  = HS[lvl];
    const int   W  = H;
    const float sc = SCL[lvl];

    const float bx1 = x1 * sc, by1 = y1 * sc;
    const float bx2 = x2 * sc, by2 = y2 * sc;
    const float rw  = fmaxf(bx2 - bx1, 1.0f);
    const float rh  = fmaxf(by2 - by1, 1.0f);
    const float bw  = rw * (1.0f / 7.0f);
    const float bh  = rh * (1.0f / 7.0f);

    // --- phase 1: separable y / x sample precompute ---
    if (tid < 14) {
        const int iy = tid;
        const float y = by1 + (float)(iy >> 1) * bh + ((float)(iy & 1) + 0.5f) * bh * 0.5f;
        const float v = (y >= -1.0f && y <= (float)H) ? 1.0f : 0.0f;
        const float yc = fminf(fmaxf(y, 0.0f), (float)(H - 1));
        int yl = (int)floorf(yc);
        if (yl > H - 2) yl = H - 2;
        ylsm[iy] = yl;
        lysm[iy] = yc - (float)yl;
        vysm[iy] = v;
    } else if (tid >= 32 && tid < 46) {
        const int ix = tid - 32;
        const float x = bx1 + (float)(ix >> 1) * bw + ((float)(ix & 1) + 0.5f) * bw * 0.5f;
        const float v = (x >= -1.0f && x <= (float)W) ? 1.0f : 0.0f;
        const float xc = fminf(fmaxf(x, 0.0f), (float)(W - 1));
        int xl = (int)floorf(xc);
        if (xl > W - 2) xl = W - 2;
        xlsm[ix] = xl;
        lxsm[ix] = xc - (float)xl;
        vxsm[ix] = v;
    }
    __syncthreads();

    // --- phase 2: per-sample combined offset + 4 bilinear weights ---
    for (int ss = tid; ss < NSAMP * NSAMP; ss += 256) {
        const int iy = ss / NSAMP;
        const int ix = ss - iy * NSAMP;
        const float ly = lysm[iy], lx = lxsm[ix];
        const float v  = vysm[iy] * vxsm[ix];
        const float hy = 1.0f - ly, hx = 1.0f - lx;
        wsm[ss]   = make_float4(hy * hx * v, hy * lx * v, ly * hx * v, ly * lx * v);
        offsm[ss] = (ylsm[iy] * W + xlsm[ix]) * NCH;
    }
    __syncthreads();

    // --- phase 3: 49 bins split over 4 bin-groups; 4 channels per thread ---
    const int cg = tid & 63;
    const int bg = tid >> 6;
    const float* fb = g_cl + OFF[lvl] + (size_t)b * H * W * NCH + cg * 4;
    const int rs = W * NCH;   // +1 feature row in floats

    for (int bin = bg; bin < 49; bin += 4) {
        const int ph = bin / 7;
        const int pw = bin - ph * 7;
        float4 acc = make_float4(0.f, 0.f, 0.f, 0.f);
        #pragma unroll
        for (int sub = 0; sub < 4; ++sub) {
            const int sI = (ph * 2 + (sub >> 1)) * NSAMP + (pw * 2 + (sub & 1));
            const float4 w = wsm[sI];
            const int    o = offsm[sI];
            const float4* p0 = (const float4*)(fb + o);
            const float4* p1 = (const float4*)(fb + o + rs);
            const float4 v00 = p0[0];
            const float4 v01 = p0[64];   // +256 floats = next x
            const float4 v10 = p1[0];
            const float4 v11 = p1[64];
            acc.x += w.x * v00.x + w.y * v01.x + w.z * v10.x + w.w * v11.x;
            acc.y += w.x * v00.y + w.y * v01.y + w.z * v10.y + w.w * v11.y;
            acc.z += w.x * v00.z + w.y * v01.z + w.z * v10.z + w.w * v11.z;
            acc.w += w.x * v00.w + w.y * v01.w + w.z * v10.w + w.w * v11.w;
        }
        const int base = (cg * 4) * 49 + bin;
        stage[base      ] = acc.x * 0.25f;
        stage[base +  49] = acc.y * 0.25f;
        stage[base +  98] = acc.z * 0.25f;
        stage[base + 147] = acc.w * 0.25f;
    }
    __syncthreads();

    // --- phase 4: fully coalesced float4 writeback of the ROI tile ---
    float4* op = (float4*)(out + (size_t)k * OUT_PER_ROI);
    const float4* sp = (const float4*)stage;
    for (int v = tid; v < OUT_PER_ROI / 4; v += 256)
        op[v] = sp[v];
}

// ---------------------------------------------------------------------------
extern "C" void kernel_launch(void* const* d_in, const int* in_sizes, int n_in,
                              void* d_out, int out_size)
{
    (void)in_sizes; (void)n_in; (void)out_size;
    const float* boxes = (const float*)d_in[4];
    float* out = (float*)d_out;

    cudaFuncSetAttribute(roi_kernel,
                         cudaFuncAttributeMaxDynamicSharedMemorySize, SMEM_BYTES);

    const int P[4]    = {40000, 10000, 2500, 625};
    const int OFFh[4] = {0, 20480000, 25600000, 26880000};
    for (int l = 0; l < 4; ++l) {
        dim3 grid((P[l] + 31) / 32, NCH / 32, NB);
        transpose_k<<<grid, dim3(32, 8)>>>((const float*)d_in[l], P[l], OFFh[l]);
    }

    roi_kernel<<<K_ROIS, 256, SMEM_BYTES>>>(boxes, out);
}